// round 13
// baseline (speedup 1.0000x reference)
#include <cuda_runtime.h>
#include <cstdint>

#define Bn 256
#define Tn 1024
#define Cn 256
#define Ln 128
#define NEP 64            // 64 epochs x 16 steps: t = 16e+1 .. 16e+16 (last guarded)
#define RROWS 32          // 2-epoch ring, slot = t & 31
#define NEGF (-1e30f)
#define EPSF (1e-7f)
#define NTH 64            // 2 warps
#define LN2F 0.6931471805599453f

// grid = 256 (one batch row per block), static smem ~45KB, 2 blocks/SM.
// warp 0: full recurrence. Lane l owns states 8l..8l+7 with its OWN scale
//         exponent E_l (alpha = A * 2^E_l). Per step: 8 linear updates + ONE
//         shfl_up; neighbor value converted frames via epoch-constant pvScale.
//         Per-lane exact pow2 renorm every 16 steps.
// warp 1: helper: cp.async prefetch of next epoch's 16 rows, per-row
//         denominator sums, blank-emission capture.
// State 256 excluded from the recurrence; reconstructed in the epilogue from
// the A255 + blank-emission histories (structure validated R4-R8).
// Per-LANE scaling (not warp-global) is required: the spread of log2(alpha)
// across all 256 states exceeds fp32's 126-bit range (this killed R2 & R12).

__device__ __forceinline__ float ex2f(float x){ float r; asm("ex2.approx.ftz.f32 %0, %1;" : "=f"(r) : "f"(x)); return r; }
__device__ __forceinline__ float lg2f(float x){ float r; asm("lg2.approx.ftz.f32 %0, %1;" : "=f"(r) : "f"(x)); return r; }

__global__ __launch_bounds__(NTH, 2)
void ctc_kernel(const void* __restrict__ yt_raw,
                const float* __restrict__ yp,
                float* __restrict__ out)
{
    __shared__ __align__(16) float ring[RROWS][Cn];  // 32KB
    __shared__ float sums[Tn];                       // per-row sum(p)+C*eps
    __shared__ float vbh[Tn];                        // row[t][255] raw; later prefix P(u)
    __shared__ float histL[Tn];                      // A255(t) at lane-31 epoch scale
    __shared__ float histE[NEP];                     // lane-31 exponent per epoch
    __shared__ float csum[64], coff[64];
    __shared__ int   labs[Ln];
    __shared__ float wredA[2], wredB[2], wredC[2];
    __shared__ float PtotS;
    __shared__ int   flag64;

    const int b    = blockIdx.x;
    const int tid  = threadIdx.x;
    const int wid  = tid >> 5;
    const int lane = tid & 31;
    const float* rowbase = yp + (size_t)b * Tn * Cn;

    if (tid == 0) flag64 = 1;

    // ---- prologue: helper warp loads rows 0..16 (each lane 32B per row) ----
    if (wid == 1) {
        for (int rr = 0; rr <= 16; ++rr) {
            unsigned sa = (unsigned)__cvta_generic_to_shared(&ring[rr][lane * 8]);
            const float* g = rowbase + (size_t)rr * Cn + lane * 8;
            asm volatile("cp.async.cg.shared.global [%0], [%1], 16;\n" :: "r"(sa), "l"(g));
            asm volatile("cp.async.cg.shared.global [%0], [%1], 16;\n" :: "r"(sa + 16), "l"(g + 4));
        }
        asm volatile("cp.async.commit_group;\n");
    }
    __syncthreads();

    // label dtype detect (int64 -> odd int32 words of first 64 pairs are 0)
    if (((const int*)yt_raw)[2 * tid + 1] != 0) flag64 = 0;
    __syncthreads();
    const int f64 = flag64;

    // stage labels through smem (proven path)
    for (int i = tid; i < Ln; i += NTH) {
        int v = f64 ? (int)((const long long*)yt_raw)[(size_t)b * Ln + i]
                    : ((const int*)yt_raw)[(size_t)b * Ln + i];
        labs[i] = v & 255;
    }
    if (wid == 1) asm volatile("cp.async.wait_group 0;\n");
    __syncthreads();

    // rec warp: per-lane labels/skips (lane l -> labels 4l..4l+3)
    int vo0 = Cn-1, vo1 = Cn-1, vo2 = Cn-1, vo3 = Cn-1;
    float sk0 = 0.f, sk1 = 0.f, sk2 = 0.f, sk3 = 0.f;
    if (wid == 0) {
        const int i0 = 4 * lane;
        vo0 = labs[i0]; vo1 = labs[i0+1]; vo2 = labs[i0+2]; vo3 = labs[i0+3];
        sk0 = (i0 >= 1 && vo0 != labs[i0-1]) ? 1.f : 0.f;
        sk1 = (vo1 != vo0) ? 1.f : 0.f;
        sk2 = (vo2 != vo1) ? 1.f : 0.f;
        sk3 = (vo3 != vo2) ? 1.f : 0.f;
    }

    // ---- init (t = 0), linear domain; per-lane frame exponent E ----
    float A0=0.f, A1=0.f, A2=0.f, A3=0.f, A4=0.f, A5=0.f, A6=0.f, A7=0.f;
    int E = 0;
    float pvScale = (lane == 0) ? 0.f : 1.f;   // lane 0 has no left neighbor
    if (wid == 0) {
        if (lane == 0) {
            A0 = ring[0][Cn - 1] + EPSF;   // state 0 (blank)
            A1 = ring[0][vo0] + EPSF;      // state 1 (label 0)
        }
    } else {
        const float4* r4 = (const float4*)ring[0];
        float4 x = r4[lane], y = r4[lane + 32];
        float part = ((x.x + x.y) + (x.z + x.w)) + ((y.x + y.y) + (y.z + y.w));
        #pragma unroll
        for (int o = 16; o; o >>= 1) part += __shfl_xor_sync(0xffffffffu, part, o);
        if (lane == 0) sums[0] = part + (float)Cn * EPSF;
    }
    __syncthreads();   // orders row-0 reads above before epoch-0 prefetch writes slot 0

    // ---- main loop: 64 epochs x 16 steps ----
    for (int e = 0; e < NEP; ++e) {
        if (wid == 0) {
            if (e) {   // per-LANE exact pow2 renorm over the lane's 8 states
                const float M = fmaxf(fmaxf(fmaxf(A0, A1), fmaxf(A2, A3)),
                                      fmaxf(fmaxf(A4, A5), fmaxf(A6, A7)));
                int d = 0;
                if (M > 0.f) d = ((__float_as_int(M) >> 23) & 255) - 127;
                const float sc = __int_as_float((127 - d) << 23);   // exact 2^-d
                A0 *= sc; A1 *= sc; A2 *= sc; A3 *= sc;
                A4 *= sc; A5 *= sc; A6 *= sc; A7 *= sc;
                E += d;
                const int Ep = __shfl_up_sync(0xffffffffu, E, 1);
                if (lane > 0)
                    pvScale = ex2f(fminf((float)(Ep - E), 100.f));  // frame converter
            }
            if (lane == 31) histE[e] = (float)E;

            #pragma unroll
            for (int jj = 0; jj < 16; ++jj) {
                const int t = 16 * e + 1 + jj;      // warp-uniform
                if (t < Tn) {
                    const float* rg = ring[t & 31];
                    // old state 8l-1 from lane l-1, converted to this lane's frame
                    const float pv = __shfl_up_sync(0xffffffffu, A7, 1) * pvScale;
                    const float vb = rg[Cn - 1] + EPSF;
                    const float v0 = rg[vo0] + EPSF, v1 = rg[vo1] + EPSF;
                    const float v2 = rg[vo2] + EPSF, v3 = rg[vo3] + EPSF;
                    A7 = fmaf(sk3, A5, A7 + A6) * v3;
                    A6 = (A6 + A5) * vb;
                    A5 = fmaf(sk2, A3, A5 + A4) * v2;
                    A4 = (A4 + A3) * vb;
                    A3 = fmaf(sk1, A1, A3 + A2) * v1;
                    A2 = (A2 + A1) * vb;
                    A1 = fmaf(sk0, pv, A1 + A0) * v0;
                    A0 = (A0 + pv) * vb;
                    if (lane == 31) histL[t] = A7;  // A255(t) at lane-31 epoch scale
                }
            }
        } else {
            // prefetch next epoch: rows 16e+17 .. 16e+32 into slots (row & 31)
            for (int rr = 0; rr < 16; ++rr) {
                const int rt = 16 * e + 17 + rr;
                if (rt < Tn) {
                    unsigned sa = (unsigned)__cvta_generic_to_shared(&ring[rt & 31][lane * 8]);
                    const float* g = rowbase + (size_t)rt * Cn + lane * 8;
                    asm volatile("cp.async.cg.shared.global [%0], [%1], 16;\n" :: "r"(sa), "l"(g));
                    asm volatile("cp.async.cg.shared.global [%0], [%1], 16;\n" :: "r"(sa + 16), "l"(g + 4));
                }
            }
            asm volatile("cp.async.commit_group;\n");
            // denominator sums + blank capture for this epoch's rows
            for (int rr = 0; rr < 16; ++rr) {
                const int t = 16 * e + 1 + rr;
                if (t < Tn) {
                    const float4* r4 = (const float4*)ring[t & 31];
                    float4 x = r4[lane], y = r4[lane + 32];
                    float part = ((x.x + x.y) + (x.z + x.w)) + ((y.x + y.y) + (y.z + y.w));
                    if (lane == 31) vbh[t] = y.w;   // row[t][255]
                    #pragma unroll
                    for (int o = 16; o; o >>= 1) part += __shfl_xor_sync(0xffffffffu, part, o);
                    if (lane == 0) sums[t] = part + (float)Cn * EPSF;
                }
            }
            asm volatile("cp.async.wait_group 0;\n");   // next epoch rows resident
        }
        __syncthreads();
    }

    // ==== epilogue: A256 reconstruction + D (proven structure) ====
    // Stage A: in-place prefix of lgb[u]=lg2(vbh[u]+eps) within 16-chunks (lgb[0]=0)
    {
        const int base = 16 * tid;
        float acc = 0.f;
        #pragma unroll
        for (int j = 0; j < 16; ++j) {
            const int u = base + j;
            const float x = (u == 0) ? 0.f : lg2f(vbh[u] + EPSF);
            acc += x;
            vbh[u] = acc;                    // vbh now holds within-chunk prefix
        }
        csum[tid] = acc;
    }
    __syncthreads();

    if (tid < 32) {     // exclusive scan of 64 chunk sums (2 per thread)
        const float c0 = csum[2*tid], c1 = csum[2*tid+1];
        const float tot = c0 + c1;
        float sc = tot;
        #pragma unroll
        for (int o = 1; o < 32; o <<= 1) {
            const float v = __shfl_up_sync(0xffffffffu, sc, o);
            if (tid >= o) sc += v;
        }
        const float ex = sc - tot;
        coff[2*tid]   = ex;
        coff[2*tid+1] = ex + c0;
        if (tid == 31) PtotS = sc;
    }
    __syncthreads();

    const float Ptot = PtotS;
    float lm = -3.0e38f;
    for (int u = tid; u < Tn - 1; u += NTH) {
        const float hl = (u == 0) ? 0.f : histL[u];
        float h = NEGF;
        if (u > 0 && hl > 0.f) h = histE[(u - 1) >> 4] + lg2f(hl);
        lm = fmaxf(lm, h + (Ptot - (coff[u >> 4] + vbh[u])));
    }
    float d2 = 0.f;
    #pragma unroll
    for (int j = 0; j < Tn / NTH; ++j) d2 += lg2f(sums[tid + NTH * j]);
    #pragma unroll
    for (int o = 16; o; o >>= 1) {
        lm = fmaxf(lm, __shfl_xor_sync(0xffffffffu, lm, o));
        d2 += __shfl_xor_sync(0xffffffffu, d2, o);
    }
    if (lane == 0) { wredA[wid] = lm; wredB[wid] = d2; }
    __syncthreads();

    const float M = fmaxf(wredA[0], wredA[1]);

    float se = 0.f;
    for (int u = tid; u < Tn - 1; u += NTH) {
        const float hl = (u == 0) ? 0.f : histL[u];
        float h = NEGF;
        if (u > 0 && hl > 0.f) h = histE[(u - 1) >> 4] + lg2f(hl);
        se += ex2f(h + (Ptot - (coff[u >> 4] + vbh[u])) - M);
    }
    #pragma unroll
    for (int o = 16; o; o >>= 1) se += __shfl_xor_sync(0xffffffffu, se, o);
    if (lane == 0) wredC[wid] = se;
    __syncthreads();

    if (tid == 0) {
        const float S  = wredC[0] + wredC[1];
        const float D2 = wredB[0] + wredB[1];
        const float a256 = M + lg2f(S);                 // A256(T-1), base-2
        const float hf = histL[Tn - 1];
        const float x = (hf > 0.f) ? histE[NEP - 1] + lg2f(hf) : NEGF;  // A255(T-1)
        const float m2 = fmaxf(x, a256);
        const float lse2 = m2 + lg2f(ex2f(x - m2) + ex2f(a256 - m2));
        out[b] = LN2F * (D2 - lse2);
    }
}

extern "C" void kernel_launch(void* const* d_in, const int* in_sizes, int n_in,
                              void* d_out, int out_size)
{
    int iy = (in_sizes[0] == Bn * Ln) ? 0 : 1;
    const void*  yt = d_in[iy];
    const float* yp = (const float*)d_in[1 - iy];
    ctc_kernel<<<Bn, NTH>>>(yt, yp, (float*)d_out);
}

// round 14
// speedup vs baseline: 1.6490x; 1.6490x over previous
#include <cuda_runtime.h>
#include <cstdint>

#define Bn 256
#define Tn 1024
#define Cn 256
#define Ln 128
#define NEP 64            // 64 epochs x 16 steps: t = 16e+1 .. 16e+16 (last guarded)
#define RROWS 48          // 3-epoch ring (current + next + loading)
#define NEGF (-1e30f)
#define EPSF (1e-7f)
#define NTH 128           // 4 warps
#define LN2F 0.6931471805599453f

// grid = 256 (one batch row per block), dynamic smem ~63KB, 2 blocks/SM.
// warp 0: recurrence. Lane l owns states 8l..8l+7 with its OWN exponent E_l
//         (alpha = A * 2^E_l); one shfl_up/step, neighbor converted by the
//         epoch-constant pvScale. Per-lane exact pow2 renorm per epoch.
//         (Per-lane scaling is REQUIRED: global scaling failed in R2/R12.)
// warp 1: loader: cp.async prefetch of epoch e+2 (16 rows), wait_group 1.
// warps 2,3: denominator sums + blank capture, 8 rows each, shfl trees
//         interleaved across rows (R13's serial trees were the bottleneck).
// State 256 excluded; reconstructed in epilogue (validated R4-R13).

__device__ __forceinline__ float ex2f(float x){ float r; asm("ex2.approx.ftz.f32 %0, %1;" : "=f"(r) : "f"(x)); return r; }
__device__ __forceinline__ float lg2f(float x){ float r; asm("lg2.approx.ftz.f32 %0, %1;" : "=f"(r) : "f"(x)); return r; }

extern __shared__ __align__(16) float smemf[];

#define OFF_RING  0                        // [RROWS][Cn] = 12288
#define OFF_SUMS  (OFF_RING + RROWS*Cn)    // [Tn]
#define OFF_VBH   (OFF_SUMS + Tn)          // [Tn]
#define OFF_HISTL (OFF_VBH + Tn)           // [Tn]
#define OFF_HISTE (OFF_HISTL + Tn)         // [NEP]
#define OFF_CSUM  (OFF_HISTE + NEP)        // [128]
#define OFF_COFF  (OFF_CSUM + 128)         // [128]
#define OFF_LABS  (OFF_COFF + 128)         // [Ln] ints
#define OFF_WREDA (OFF_LABS + Ln)          // [4]
#define OFF_WREDB (OFF_WREDA + 4)
#define OFF_WREDC (OFF_WREDB + 4)
#define OFF_PTOT  (OFF_WREDC + 4)
#define OFF_F64   (OFF_PTOT + 1)
#define SMEM_FLOATS (OFF_F64 + 1)

__global__ __launch_bounds__(NTH, 2)
void ctc_kernel(const void* __restrict__ yt_raw,
                const float* __restrict__ yp,
                float* __restrict__ out)
{
    float* ring  = smemf + OFF_RING;     // ring[sl*Cn + c]
    float* sums  = smemf + OFF_SUMS;
    float* vbh   = smemf + OFF_VBH;
    float* histL = smemf + OFF_HISTL;
    float* histE = smemf + OFF_HISTE;
    float* csum  = smemf + OFF_CSUM;
    float* coff  = smemf + OFF_COFF;
    int*   labs  = (int*)(smemf + OFF_LABS);
    float* wredA = smemf + OFF_WREDA;
    float* wredB = smemf + OFF_WREDB;
    float* wredC = smemf + OFF_WREDC;
    float* PtotS = smemf + OFF_PTOT;
    int*   flag64 = (int*)(smemf + OFF_F64);

    const int b    = blockIdx.x;
    const int tid  = threadIdx.x;
    const int wid  = tid >> 5;
    const int lane = tid & 31;
    const float* rowbase = yp + (size_t)b * Tn * Cn;

    if (tid == 0) *flag64 = 1;

    // ---- prologue: loader warp loads rows 0..16 (group A), 17..32 (group B) ----
    if (wid == 1) {
        for (int rr = 0; rr <= 16; ++rr) {
            unsigned sa = (unsigned)__cvta_generic_to_shared(&ring[rr * Cn + lane * 8]);
            const float* g = rowbase + (size_t)rr * Cn + lane * 8;
            asm volatile("cp.async.cg.shared.global [%0], [%1], 16;\n" :: "r"(sa), "l"(g));
            asm volatile("cp.async.cg.shared.global [%0], [%1], 16;\n" :: "r"(sa + 16), "l"(g + 4));
        }
        asm volatile("cp.async.commit_group;\n");
        for (int rr = 17; rr <= 32; ++rr) {
            unsigned sa = (unsigned)__cvta_generic_to_shared(&ring[rr * Cn + lane * 8]);
            const float* g = rowbase + (size_t)rr * Cn + lane * 8;
            asm volatile("cp.async.cg.shared.global [%0], [%1], 16;\n" :: "r"(sa), "l"(g));
            asm volatile("cp.async.cg.shared.global [%0], [%1], 16;\n" :: "r"(sa + 16), "l"(g + 4));
        }
        asm volatile("cp.async.commit_group;\n");
        asm volatile("cp.async.wait_group 1;\n");   // group A (rows 0..16) resident
    }
    __syncthreads();

    // label dtype detect (int64 -> odd int32 words of first 128 pairs are 0)
    if (((const int*)yt_raw)[2 * tid + 1] != 0) *flag64 = 0;
    __syncthreads();
    const int f64 = *flag64;

    // stage labels through smem
    if (tid < Ln) {
        int v = f64 ? (int)((const long long*)yt_raw)[(size_t)b * Ln + tid]
                    : ((const int*)yt_raw)[(size_t)b * Ln + tid];
        labs[tid] = v & 255;
    }
    __syncthreads();

    // rec warp: per-lane labels/skips (lane l -> labels 4l..4l+3)
    int vo0 = Cn-1, vo1 = Cn-1, vo2 = Cn-1, vo3 = Cn-1;
    float sk0 = 0.f, sk1 = 0.f, sk2 = 0.f, sk3 = 0.f;
    if (wid == 0) {
        const int i0 = 4 * lane;
        vo0 = labs[i0]; vo1 = labs[i0+1]; vo2 = labs[i0+2]; vo3 = labs[i0+3];
        sk0 = (i0 >= 1 && vo0 != labs[i0-1]) ? 1.f : 0.f;
        sk1 = (vo1 != vo0) ? 1.f : 0.f;
        sk2 = (vo2 != vo1) ? 1.f : 0.f;
        sk3 = (vo3 != vo2) ? 1.f : 0.f;
    }

    // ---- init (t = 0), linear domain; per-lane frame exponent E ----
    float A0=0.f, A1=0.f, A2=0.f, A3=0.f, A4=0.f, A5=0.f, A6=0.f, A7=0.f;
    int E = 0;
    float pvScale = (lane == 0) ? 0.f : 1.f;
    if (wid == 0) {
        if (lane == 0) {
            A0 = ring[Cn - 1] + EPSF;      // state 0 (blank), row 0 in slot 0
            A1 = ring[vo0] + EPSF;         // state 1 (label 0)
        }
    } else if (wid == 2) {                 // row-0 denominator
        const float4* r4 = (const float4*)ring;
        float4 x = r4[lane], y = r4[lane + 32];
        float part = ((x.x + x.y) + (x.z + x.w)) + ((y.x + y.y) + (y.z + y.w));
        #pragma unroll
        for (int o = 16; o; o >>= 1) part += __shfl_xor_sync(0xffffffffu, part, o);
        if (lane == 0) sums[0] = part + (float)Cn * EPSF;
    }
    __syncthreads();   // row-0 reads above complete before epoch-0 loader writes slot 0

    // ---- main loop: 64 epochs x 16 steps ----
    int s0 = 1;        // slot of row 16e+1: (16e+1) % 48, maintained incrementally
    for (int e = 0; e < NEP; ++e) {
        if (wid == 0) {
            if (e) {   // per-LANE exact pow2 renorm over the lane's 8 states
                const float M = fmaxf(fmaxf(fmaxf(A0, A1), fmaxf(A2, A3)),
                                      fmaxf(fmaxf(A4, A5), fmaxf(A6, A7)));
                int d = 0;
                if (M > 0.f) d = ((__float_as_int(M) >> 23) & 255) - 127;
                const float sc = __int_as_float((127 - d) << 23);   // exact 2^-d
                A0 *= sc; A1 *= sc; A2 *= sc; A3 *= sc;
                A4 *= sc; A5 *= sc; A6 *= sc; A7 *= sc;
                E += d;
                const int Ep = __shfl_up_sync(0xffffffffu, E, 1);
                if (lane > 0)
                    pvScale = ex2f(fminf((float)(Ep - E), 100.f));
            }
            if (lane == 31) histE[e] = (float)E;

            int sl = s0;
            #pragma unroll
            for (int jj = 0; jj < 16; ++jj) {
                const int t = 16 * e + 1 + jj;      // warp-uniform
                if (t < Tn) {
                    const float* rg = &ring[sl * Cn];
                    const float pv = __shfl_up_sync(0xffffffffu, A7, 1) * pvScale;
                    const float vb = rg[Cn - 1] + EPSF;
                    const float v0 = rg[vo0] + EPSF, v1 = rg[vo1] + EPSF;
                    const float v2 = rg[vo2] + EPSF, v3 = rg[vo3] + EPSF;
                    A7 = fmaf(sk3, A5, A7 + A6) * v3;
                    A6 = (A6 + A5) * vb;
                    A5 = fmaf(sk2, A3, A5 + A4) * v2;
                    A4 = (A4 + A3) * vb;
                    A3 = fmaf(sk1, A1, A3 + A2) * v1;
                    A2 = (A2 + A1) * vb;
                    A1 = fmaf(sk0, pv, A1 + A0) * v0;
                    A0 = (A0 + pv) * vb;
                    if (lane == 31) histL[t] = A7;  // A255(t) at lane-31 frame
                }
                ++sl; if (sl >= RROWS) sl -= RROWS;
            }
        }
        else if (wid == 1) {
            // prefetch epoch e+2: rows 16e+33 .. 16e+48 (slots disjoint from e, e+1)
            int sl = s0 + 32; if (sl >= RROWS) sl -= RROWS;
            for (int rr = 0; rr < 16; ++rr) {
                const int rt = 16 * e + 33 + rr;
                if (rt < Tn) {
                    unsigned sa = (unsigned)__cvta_generic_to_shared(&ring[sl * Cn + lane * 8]);
                    const float* g = rowbase + (size_t)rt * Cn + lane * 8;
                    asm volatile("cp.async.cg.shared.global [%0], [%1], 16;\n" :: "r"(sa), "l"(g));
                    asm volatile("cp.async.cg.shared.global [%0], [%1], 16;\n" :: "r"(sa + 16), "l"(g + 4));
                }
                ++sl; if (sl >= RROWS) sl -= RROWS;
            }
            asm volatile("cp.async.commit_group;\n");
            asm volatile("cp.async.wait_group 1;\n");   // epoch e+1 rows resident
        }
        else {
            // sums warps: w2 rows 0..7, w3 rows 8..15 of this epoch; trees interleaved
            const int rbase = (wid == 2) ? 0 : 8;
            float part[8];
            int sl = s0 + rbase; if (sl >= RROWS) sl -= RROWS;
            #pragma unroll
            for (int rr = 0; rr < 8; ++rr) {
                const int t = 16 * e + 1 + rbase + rr;
                if (t < Tn) {
                    const float4* r4 = (const float4*)&ring[sl * Cn];
                    float4 x = r4[lane], y = r4[lane + 32];
                    part[rr] = ((x.x + x.y) + (x.z + x.w)) + ((y.x + y.y) + (y.z + y.w));
                    if (lane == 31) vbh[t] = y.w;       // row[t][255]
                } else part[rr] = 0.f;
                ++sl; if (sl >= RROWS) sl -= RROWS;
            }
            #pragma unroll
            for (int o = 16; o; o >>= 1) {
                #pragma unroll
                for (int rr = 0; rr < 8; ++rr)
                    part[rr] += __shfl_xor_sync(0xffffffffu, part[rr], o);
            }
            if (lane == 0) {
                #pragma unroll
                for (int rr = 0; rr < 8; ++rr) {
                    const int t = 16 * e + 1 + rbase + rr;
                    if (t < Tn) sums[t] = part[rr] + (float)Cn * EPSF;
                }
            }
        }
        __syncthreads();
        s0 += 16; if (s0 >= RROWS) s0 -= RROWS;
    }

    // ==== epilogue: A256 reconstruction + D (proven structure; 128 threads) ====
    {
        const int base = 8 * tid;
        float acc = 0.f;
        #pragma unroll
        for (int j = 0; j < 8; ++j) {
            const int u = base + j;
            const float x = (u == 0) ? 0.f : lg2f(vbh[u] + EPSF);
            acc += x;
            vbh[u] = acc;                    // in-place within-chunk prefix
        }
        csum[tid] = acc;
    }
    __syncthreads();

    if (tid < 32) {     // exclusive scan of 128 chunk sums (4 per thread)
        const float c0 = csum[4*tid], c1 = csum[4*tid+1],
                    c2 = csum[4*tid+2], c3 = csum[4*tid+3];
        const float tot = ((c0 + c1) + (c2 + c3));
        float sc = tot;
        #pragma unroll
        for (int o = 1; o < 32; o <<= 1) {
            const float v = __shfl_up_sync(0xffffffffu, sc, o);
            if (tid >= o) sc += v;
        }
        const float ex = sc - tot;
        coff[4*tid]   = ex;
        coff[4*tid+1] = ex + c0;
        coff[4*tid+2] = ex + c0 + c1;
        coff[4*tid+3] = ex + c0 + c1 + c2;
        if (tid == 31) *PtotS = sc;
    }
    __syncthreads();

    const float Ptot = *PtotS;
    float lm = -3.0e38f;
    for (int u = tid; u < Tn - 1; u += NTH) {
        const float hl = (u == 0) ? 0.f : histL[u];
        float h = NEGF;
        if (u > 0 && hl > 0.f) h = histE[(u - 1) >> 4] + lg2f(hl);
        lm = fmaxf(lm, h + (Ptot - (coff[u >> 3] + vbh[u])));
    }
    float d2 = 0.f;
    #pragma unroll
    for (int j = 0; j < Tn / NTH; ++j) d2 += lg2f(sums[tid + NTH * j]);
    #pragma unroll
    for (int o = 16; o; o >>= 1) {
        lm = fmaxf(lm, __shfl_xor_sync(0xffffffffu, lm, o));
        d2 += __shfl_xor_sync(0xffffffffu, d2, o);
    }
    if (lane == 0) { wredA[wid] = lm; wredB[wid] = d2; }
    __syncthreads();

    const float M = fmaxf(fmaxf(wredA[0], wredA[1]), fmaxf(wredA[2], wredA[3]));

    float se = 0.f;
    for (int u = tid; u < Tn - 1; u += NTH) {
        const float hl = (u == 0) ? 0.f : histL[u];
        float h = NEGF;
        if (u > 0 && hl > 0.f) h = histE[(u - 1) >> 4] + lg2f(hl);
        se += ex2f(h + (Ptot - (coff[u >> 3] + vbh[u])) - M);
    }
    #pragma unroll
    for (int o = 16; o; o >>= 1) se += __shfl_xor_sync(0xffffffffu, se, o);
    if (lane == 0) wredC[wid] = se;
    __syncthreads();

    if (tid == 0) {
        float S = 0.f, D2 = 0.f;
        #pragma unroll
        for (int w = 0; w < 4; ++w) { S += wredC[w]; D2 += wredB[w]; }
        const float a256 = M + lg2f(S);                 // A256(T-1), base-2
        const float hf = histL[Tn - 1];
        const float x = (hf > 0.f) ? histE[NEP - 1] + lg2f(hf) : NEGF;  // A255(T-1)
        const float m2 = fmaxf(x, a256);
        const float lse2 = m2 + lg2f(ex2f(x - m2) + ex2f(a256 - m2));
        out[b] = LN2F * (D2 - lse2);
    }
}

extern "C" void kernel_launch(void* const* d_in, const int* in_sizes, int n_in,
                              void* d_out, int out_size)
{
    int iy = (in_sizes[0] == Bn * Ln) ? 0 : 1;
    const void*  yt = d_in[iy];
    const float* yp = (const float*)d_in[1 - iy];
    const size_t smem = SMEM_FLOATS * sizeof(float);
    cudaFuncSetAttribute(ctc_kernel, cudaFuncAttributeMaxDynamicSharedMemorySize, (int)smem);
    ctc_kernel<<<Bn, NTH, smem>>>(yt, yp, (float*)d_out);
}